// round 11
// baseline (speedup 1.0000x reference)
#include <cuda_runtime.h>
#include <cuda_fp16.h>
#include <mma.h>
#include <cstdint>

using namespace nvcuda;

// Shape: B=16, n=4096, D=1024. Tokens = 65536.
#define B_SZ   16
#define N_TOK  4096
#define D_DIM  1024
#define NTOK_TOTAL (B_SZ * N_TOK)

#define NCHUNKS 4          // 1024 / BN
#define BM 128
#define BN 256
#define BK 64
#define KSTEPS (D_DIM / BK)   // 16

#define XPAD 72            // fp16 elems per x-row in smem (64 + 8 pad) = 144 B
#define WPAD 264           // fp16 elems per w-row in smem (256 + 8 pad) = 528 B
#define EPAD 260           // f32 elems per epilogue row

// Scratch (__device__ globals: allocation-free rule)
__device__ float g_part[NCHUNKS][NTOK_TOTAL];
__device__ __half g_xf[(size_t)NTOK_TOTAL * D_DIM];    // fp16(x)
__device__ __half g_Wh[D_DIM * D_DIM];                 // fp16(W1) [k][e]

// smem layout (bytes)
#define ST_XH 0                      // 128 * 144 = 18432
#define ST_WH 18432                  // 64 * 528  = 33792
#define STAGE_B 52224
#define NSLOT 3
#define SM_B1 (NSLOT * STAGE_B)      // 156672 (epilogue 133120 aliases slots)
#define SM_W2 (SM_B1 + 1024)
#define SMEM_TOTAL (SM_W2 + 1024)    // 158720

__device__ __forceinline__ uint32_t smem_u32(const void* p) {
    uint32_t a;
    asm("{ .reg .u64 t; cvta.to.shared.u64 t, %1; cvt.u32.u64 %0, t; }" : "=r"(a) : "l"(p));
    return a;
}
#define CP16(dst, src) \
    asm volatile("cp.async.cg.shared.global [%0], [%1], 16;" :: "r"(dst), "l"(src) : "memory")
#define CP_COMMIT() asm volatile("cp.async.commit_group;" ::: "memory")
#define CP_WAIT(n)  asm volatile("cp.async.wait_group %0;" :: "n"(n) : "memory")

// ---------------------------------------------------------------------------
// Prep: x -> fp16, W1 -> fp16.
// ---------------------------------------------------------------------------
__global__ __launch_bounds__(256)
void prep_x_kernel(const float* __restrict__ x)
{
    const size_t i4 = (size_t)blockIdx.x * 256 + threadIdx.x;   // float4 index
    float4 v = ((const float4*)x)[i4];
    ((__half2*)g_xf)[i4 * 2]     = __floats2half2_rn(v.x, v.y);
    ((__half2*)g_xf)[i4 * 2 + 1] = __floats2half2_rn(v.z, v.w);
}

__global__ __launch_bounds__(256)
void prep_w_kernel(const float* __restrict__ W1)
{
    const size_t i4 = (size_t)blockIdx.x * 256 + threadIdx.x;
    float4 v = ((const float4*)W1)[i4];
    ((__half2*)g_Wh)[i4 * 2]     = __floats2half2_rn(v.x, v.y);
    ((__half2*)g_Wh)[i4 * 2 + 1] = __floats2half2_rn(v.z, v.w);
}

// ---------------------------------------------------------------------------
// Kernel A: fp16 wmma logits GEMM, cp.async pipelined.
// Grid (4, 512): x = n-chunk (256 feats), y = m-tile (128 tokens).
// 8 warps, warp tile 64x64 (2m x 4n). K streamed in 16 stages of BK=64,
// 3 smem slots, pipeline depth 2, ONE barrier per stage.
// ---------------------------------------------------------------------------
__global__ __launch_bounds__(256, 1)
void logits_wmma_kernel(const float* __restrict__ b1,
                        const float* __restrict__ W2)
{
    extern __shared__ char smem[];
    const uint32_t sb = smem_u32(smem);
    const int tid = threadIdx.x;
    const int wid = tid >> 5;
    const int n0  = blockIdx.x * BN;
    const int m0  = blockIdx.y * BM;

    float* s_b1 = (float*)(smem + SM_B1);
    float* s_w2 = (float*)(smem + SM_W2);
    if (tid < 256) { s_b1[tid] = b1[n0 + tid]; s_w2[tid] = W2[n0 + tid]; }

    // per-thread cp.async assignments
    // x: 128 rows x 64 fp16 = 128B/row = 8x16B chunks... wait: 64 fp16 = 128B
    //    -> 4 chunks/row of 16B? 128B = 8 chunks. Recompute: 64 fp16 * 2 = 128 B
    //    = 8 chunks of 16B. 128 rows * 8 = 1024 chunks, 4 per thread.
    // W: 64 rows x 256 fp16 = 512B/row = 32 chunks; 2048 chunks, 8 per thread.
    auto issue_stage = [&](int kt, int slot) {
        const int k0 = kt * BK;
        const uint32_t s = sb + slot * STAGE_B;
        #pragma unroll
        for (int u = 0; u < 4; u++) {
            const int c   = tid * 4 + u;        // 0..1023
            const int row = c >> 3;             // 0..127
            const int cc  = c & 7;              // 16B chunk in row
            CP16(s + ST_XH + row * (XPAD * 2) + cc * 16,
                 g_xf + (size_t)(m0 + row) * D_DIM + k0 + cc * 8);
        }
        #pragma unroll
        for (int u = 0; u < 8; u++) {
            const int c   = tid * 8 + u;        // 0..2047
            const int row = c >> 5;             // 0..63 (k row)
            const int cc  = c & 31;             // 16B chunk in row
            CP16(s + ST_WH + row * (WPAD * 2) + cc * 16,
                 g_Wh + (size_t)(k0 + row) * D_DIM + n0 + cc * 8);
        }
        CP_COMMIT();
    };

    // warp tile: wm in {0,1} (64 rows), wn in {0..3} (64 cols)
    const int wm = wid & 1;
    const int wn = wid >> 1;

    wmma::fragment<wmma::accumulator, 16, 16, 16, float> acc[4][4];
    #pragma unroll
    for (int i = 0; i < 4; i++)
        #pragma unroll
        for (int j = 0; j < 4; j++) wmma::fill_fragment(acc[i][j], 0.f);

    issue_stage(0, 0);
    issue_stage(1, 1);

    #pragma unroll 1
    for (int kt = 0; kt < KSTEPS; kt++) {
        CP_WAIT(1);
        __syncthreads();    // stage kt ready for all; also orders compute(kt-1)
                            // before issue(kt+2) overwrites slot (kt+2)%3
        if (kt + 2 < KSTEPS) issue_stage(kt + 2, (kt + 2) % NSLOT);
        else                 CP_COMMIT();

        const char* s = smem + (kt % NSLOT) * STAGE_B;
        const __half (*xh)[XPAD] = (const __half(*)[XPAD])(s + ST_XH);
        const __half (*wh)[WPAD] = (const __half(*)[WPAD])(s + ST_WH);

        #pragma unroll
        for (int kk = 0; kk < BK; kk += 16) {
            wmma::fragment<wmma::matrix_a, 16, 16, 16, __half, wmma::row_major> ah[4];
            #pragma unroll
            for (int i = 0; i < 4; i++)
                wmma::load_matrix_sync(ah[i], &xh[wm * 64 + i * 16][kk], XPAD);
            #pragma unroll
            for (int j = 0; j < 4; j++) {
                wmma::fragment<wmma::matrix_b, 16, 16, 16, __half, wmma::row_major> bh;
                wmma::load_matrix_sync(bh, &wh[kk][wn * 64 + j * 16], WPAD);
                #pragma unroll
                for (int i = 0; i < 4; i++)
                    wmma::mma_sync(acc[i][j], ah[i], bh, acc[i][j]);
            }
        }
        // no trailing barrier: next iteration's barrier provides WAR ordering
    }

    // epilogue: acc -> smem (aliases stage slots), reduce against b1/w2
    CP_WAIT(0);
    __syncthreads();
    float (*ep)[EPAD] = (float(*)[EPAD])smem;
    #pragma unroll
    for (int i = 0; i < 4; i++)
        #pragma unroll
        for (int j = 0; j < 4; j++)
            wmma::store_matrix_sync(&ep[wm * 64 + i * 16][wn * 64 + j * 16],
                                    acc[i][j], EPAD, wmma::mem_row_major);
    __syncthreads();

    const int row  = tid >> 1;
    const int half = tid & 1;
    float v = 0.f;
    #pragma unroll 8
    for (int c = 0; c < 128; c++) {
        const int e = half * 128 + c;
        float t = ep[row][e] + s_b1[e];
        t = fmaxf(t, 0.f);
        v = fmaf(t, s_w2[e], v);
    }
    v += __shfl_xor_sync(0xffffffffu, v, 1);
    if (half == 0) g_part[blockIdx.x][(size_t)m0 + row] = v;
}

// ---------------------------------------------------------------------------
// Kernel B: sum partials, 2x2 window softmax + weighted sum. (b2 shift-inv.)
// ---------------------------------------------------------------------------
__global__ __launch_bounds__(256)
void pool_kernel(const float* __restrict__ x, float* __restrict__ out)
{
    const int br = blockIdx.x;
    const int b  = br >> 10;
    const int r  = br & 1023;
    const int i  = r >> 5;
    const int j  = r & 31;
    const int t00 = (i * 2) * 64 + (j * 2);
    const int tok[4] = {t00, t00 + 1, t00 + 64, t00 + 65};

    float l[4];
    #pragma unroll
    for (int k = 0; k < 4; k++) {
        const int t = b * N_TOK + tok[k];
        float s = 0.f;
        #pragma unroll
        for (int c = 0; c < NCHUNKS; c++) s += g_part[c][t];
        l[k] = s;
    }
    float mx = fmaxf(fmaxf(l[0], l[1]), fmaxf(l[2], l[3]));
    float e0 = __expf(l[0] - mx), e1 = __expf(l[1] - mx);
    float e2 = __expf(l[2] - mx), e3 = __expf(l[3] - mx);
    float inv = 1.f / (e0 + e1 + e2 + e3);
    float a0 = e0 * inv, a1 = e1 * inv, a2 = e2 * inv, a3 = e3 * inv;

    const size_t xb = (size_t)b * N_TOK * D_DIM;
    const float4* x0 = (const float4*)(x + xb + (size_t)tok[0] * D_DIM);
    const float4* x1 = (const float4*)(x + xb + (size_t)tok[1] * D_DIM);
    const float4* x2 = (const float4*)(x + xb + (size_t)tok[2] * D_DIM);
    const float4* x3 = (const float4*)(x + xb + (size_t)tok[3] * D_DIM);
    float4* o = (float4*)(out + (size_t)br * D_DIM);

    const int d = threadIdx.x;
    float4 v0 = x0[d], v1 = x1[d], v2 = x2[d], v3 = x3[d];
    float4 ov;
    ov.x = a0 * v0.x + a1 * v1.x + a2 * v2.x + a3 * v3.x;
    ov.y = a0 * v0.y + a1 * v1.y + a2 * v2.y + a3 * v3.y;
    ov.z = a0 * v0.z + a1 * v1.z + a2 * v2.z + a3 * v3.z;
    ov.w = a0 * v0.w + a1 * v1.w + a2 * v2.w + a3 * v3.w;
    o[d] = ov;
}

// ---------------------------------------------------------------------------
extern "C" void kernel_launch(void* const* d_in, const int* in_sizes, int n_in,
                              void* d_out, int out_size)
{
    const float* x  = (const float*)d_in[0];
    const float* W1 = (const float*)d_in[1];
    const float* b1 = (const float*)d_in[2];
    const float* W2 = (const float*)d_in[3];
    float* out = (float*)d_out;

    cudaFuncSetAttribute(logits_wmma_kernel,
                         cudaFuncAttributeMaxDynamicSharedMemorySize, SMEM_TOTAL);

    prep_x_kernel<<<(NTOK_TOTAL * (D_DIM / 4)) / 256, 256>>>(x);
    prep_w_kernel<<<(D_DIM * (D_DIM / 4)) / 256, 256>>>(W1);
    logits_wmma_kernel<<<dim3(NCHUNKS, NTOK_TOTAL / BM), 256, SMEM_TOTAL>>>(b1, W2);
    pool_kernel<<<B_SZ * (N_TOK / 4), 256>>>(x, out);
}

// round 14
// speedup vs baseline: 1.0356x; 1.0356x over previous
#include <cuda_runtime.h>
#include <cuda_fp16.h>
#include <mma.h>
#include <cstdint>

using namespace nvcuda;

// Shape: B=16, n=4096, D=1024. Tokens = 65536.
#define B_SZ   16
#define N_TOK  4096
#define D_DIM  1024
#define NTOK_TOTAL (B_SZ * N_TOK)

#define NCHUNKS 8          // 1024 / BN
#define BM 128
#define BN 128
#define BK 32
#define KSTEPS (D_DIM / BK)   // 32

#define XPAD 40            // fp16 per x-row in smem (32 + 8 pad) = 80 B
#define WPAD 136           // fp16 per w-row in smem (128 + 8 pad) = 272 B
#define EPAD 132           // f32 per epilogue row (two-phase, 64 rows)

// Scratch (__device__ globals: allocation-free rule)
__device__ float g_part[NCHUNKS][NTOK_TOTAL];
__device__ __half g_xf[(size_t)NTOK_TOTAL * D_DIM];    // fp16(x)
__device__ __half g_Wh[D_DIM * D_DIM];                 // fp16(W1) [k][e]

// smem layout (bytes)
#define ST_XH 0                      // 128 * 80  = 10240
#define ST_WH 10240                  // 32 * 272  = 8704
#define STAGE_B 18944
#define NSLOT 3
#define SM_B1 (NSLOT * STAGE_B)      // 56832; epilogue [64][132] f32 = 33792 aliases slots
#define SM_W2 (SM_B1 + 512)
#define SMEM_TOTAL (SM_W2 + 512)     // 57856  -> 2 CTAs/SM
 
__device__ __forceinline__ uint32_t smem_u32(const void* p) {
    uint32_t a;
    asm("{ .reg .u64 t; cvta.to.shared.u64 t, %1; cvt.u32.u64 %0, t; }" : "=r"(a) : "l"(p));
    return a;
}
#define CP16(dst, src) \
    asm volatile("cp.async.cg.shared.global [%0], [%1], 16;" :: "r"(dst), "l"(src) : "memory")
#define CP_COMMIT() asm volatile("cp.async.commit_group;" ::: "memory")
#define CP_WAIT(n)  asm volatile("cp.async.wait_group %0;" :: "n"(n) : "memory")

// ---------------------------------------------------------------------------
// Prep: x -> fp16, W1 -> fp16.
// ---------------------------------------------------------------------------
__global__ __launch_bounds__(256)
void prep_x_kernel(const float* __restrict__ x)
{
    const size_t i4 = (size_t)blockIdx.x * 256 + threadIdx.x;   // float4 index
    float4 v = ((const float4*)x)[i4];
    ((__half2*)g_xf)[i4 * 2]     = __floats2half2_rn(v.x, v.y);
    ((__half2*)g_xf)[i4 * 2 + 1] = __floats2half2_rn(v.z, v.w);
}

__global__ __launch_bounds__(256)
void prep_w_kernel(const float* __restrict__ W1)
{
    const size_t i4 = (size_t)blockIdx.x * 256 + threadIdx.x;
    float4 v = ((const float4*)W1)[i4];
    ((__half2*)g_Wh)[i4 * 2]     = __floats2half2_rn(v.x, v.y);
    ((__half2*)g_Wh)[i4 * 2 + 1] = __floats2half2_rn(v.z, v.w);
}

// ---------------------------------------------------------------------------
// Kernel A: fp16 wmma logits GEMM, cp.async pipelined, 2 CTAs/SM.
// Grid (8, 512): x = n-chunk (128 feats), y = m-tile (128 tokens).
// 128 threads, 4 warps, warp tile 64x64 (2m x 2n). K in 32 stages of BK=32,
// 3 smem slots, depth 2, two barriers per stage (R10-proven structure).
// ---------------------------------------------------------------------------
__global__ __launch_bounds__(128, 2)
void logits_wmma_kernel(const float* __restrict__ b1,
                        const float* __restrict__ W2)
{
    extern __shared__ char smem[];
    const uint32_t sb = smem_u32(smem);
    const int tid = threadIdx.x;
    const int wid = tid >> 5;
    const int n0  = blockIdx.x * BN;
    const int m0  = blockIdx.y * BM;

    float* s_b1 = (float*)(smem + SM_B1);
    float* s_w2 = (float*)(smem + SM_W2);
    if (tid < 128) { s_b1[tid] = b1[n0 + tid]; s_w2[tid] = W2[n0 + tid]; }

    // cp.async: x = 512 16B-chunks (4/thread), W = 512 16B-chunks (4/thread)
    auto issue_stage = [&](int kt, int slot) {
        const int k0 = kt * BK;
        const uint32_t s = sb + slot * STAGE_B;
        #pragma unroll
        for (int u = 0; u < 4; u++) {
            const int c   = tid * 4 + u;        // 0..511
            const int row = c >> 2;             // 0..127
            const int cc  = c & 3;              // 16B chunk in 64B row
            CP16(s + ST_XH + row * (XPAD * 2) + cc * 16,
                 g_xf + (size_t)(m0 + row) * D_DIM + k0 + cc * 8);
        }
        #pragma unroll
        for (int u = 0; u < 4; u++) {
            const int c   = tid * 4 + u;        // 0..511
            const int row = c >> 4;             // 0..31 (k row)
            const int cc  = c & 15;             // 16B chunk in 256B row
            CP16(s + ST_WH + row * (WPAD * 2) + cc * 16,
                 g_Wh + (size_t)(k0 + row) * D_DIM + n0 + cc * 8);
        }
        CP_COMMIT();
    };

    // warp tile: wm in {0,1} (64 rows), wn in {0,1} (64 cols)
    const int wm = wid & 1;
    const int wn = wid >> 1;

    wmma::fragment<wmma::accumulator, 16, 16, 16, float> acc[4][4];
    #pragma unroll
    for (int i = 0; i < 4; i++)
        #pragma unroll
        for (int j = 0; j < 4; j++) wmma::fill_fragment(acc[i][j], 0.f);

    issue_stage(0, 0);
    issue_stage(1, 1);

    #pragma unroll 2
    for (int kt = 0; kt < KSTEPS; kt++) {
        CP_WAIT(1);
        __syncthreads();
        if (kt + 2 < KSTEPS) issue_stage(kt + 2, (kt + 2) % NSLOT);
        else                 CP_COMMIT();

        const char* s = smem + (kt % NSLOT) * STAGE_B;
        const __half (*xh)[XPAD] = (const __half(*)[XPAD])(s + ST_XH);
        const __half (*wh)[WPAD] = (const __half(*)[WPAD])(s + ST_WH);

        #pragma unroll
        for (int kk = 0; kk < BK; kk += 16) {
            wmma::fragment<wmma::matrix_a, 16, 16, 16, __half, wmma::row_major> ah[4];
            #pragma unroll
            for (int i = 0; i < 4; i++)
                wmma::load_matrix_sync(ah[i], &xh[wm * 64 + i * 16][kk], XPAD);
            #pragma unroll
            for (int j = 0; j < 4; j++) {
                wmma::fragment<wmma::matrix_b, 16, 16, 16, __half, wmma::row_major> bh;
                wmma::load_matrix_sync(bh, &wh[kk][wn * 64 + j * 16], WPAD);
                #pragma unroll
                for (int i = 0; i < 4; i++)
                    wmma::mma_sync(acc[i][j], ah[i], bh, acc[i][j]);
            }
        }
        __syncthreads();
    }

    // two-phase epilogue: 64 rows at a time into [64][EPAD] (aliases slots)
    CP_WAIT(0);
    __syncthreads();
    float (*ep)[EPAD] = (float(*)[EPAD])smem;
    #pragma unroll 1
    for (int p = 0; p < 2; p++) {
        if (wm == p) {
            #pragma unroll
            for (int i = 0; i < 4; i++)
                #pragma unroll
                for (int j = 0; j < 4; j++)
                    wmma::store_matrix_sync(&ep[i * 16][wn * 64 + j * 16],
                                            acc[i][j], EPAD, wmma::mem_row_major);
        }
        __syncthreads();
        // 128 threads reduce 64 rows x 128 cols
        const int row  = tid >> 1;            // 0..63
        const int half = tid & 1;
        float v = 0.f;
        #pragma unroll 8
        for (int c = 0; c < 64; c++) {
            const int e = half * 64 + c;
            float t = ep[row][e] + s_b1[e];
            t = fmaxf(t, 0.f);
            v = fmaf(t, s_w2[e], v);
        }
        v += __shfl_xor_sync(0xffffffffu, v, 1);
        if (half == 0) g_part[blockIdx.x][(size_t)m0 + p * 64 + row] = v;
        __syncthreads();
    }
}

// ---------------------------------------------------------------------------
// Kernel B: sum partials, 2x2 window softmax + weighted sum over fp16 x.
// (b2 omitted: softmax shift-invariant.)
// ---------------------------------------------------------------------------
__global__ __launch_bounds__(256)
void pool_kernel(float* __restrict__ out)
{
    const int br = blockIdx.x;
    const int b  = br >> 10;
    const int r  = br & 1023;
    const int i  = r >> 5;
    const int j  = r & 31;
    const int t00 = (i * 2) * 64 + (j * 2);
    const int tok[4] = {t00, t00 + 1, t00 + 64, t00 + 65};

    float l[4];
    #pragma unroll
    for (int k = 0; k < 4; k++) {
        const int t = b * N_TOK + tok[k];
        float s = 0.f;
        #pragma unroll
        for (int c = 0; c < NCHUNKS; c++) s += g_part[c][t];
        l[k] = s;
    }
    float mx = fmaxf(fmaxf(l[0], l[1]), fmaxf(l[2], l[3]));
    float e0 = __expf(l[0] - mx), e1 = __expf(l[1] - mx);
    float e2 = __expf(l[2] - mx), e3 = __expf(l[3] - mx);
    float inv = 1.f / (e0 + e1 + e2 + e3);
    const float a[4] = {e0 * inv, e1 * inv, e2 * inv, e3 * inv};

    const size_t xb = (size_t)b * N_TOK * D_DIM;
    const int d = threadIdx.x;               // 4 floats per thread
    float4 ov = {0.f, 0.f, 0.f, 0.f};
    #pragma unroll
    for (int k = 0; k < 4; k++) {
        const __half2* xr = (const __half2*)(g_xf + xb + (size_t)tok[k] * D_DIM);
        float2 p0 = __half22float2(xr[d * 2]);
        float2 p1 = __half22float2(xr[d * 2 + 1]);
        ov.x = fmaf(a[k], p0.x, ov.x);
        ov.y = fmaf(a[k], p0.y, ov.y);
        ov.z = fmaf(a[k], p1.x, ov.z);
        ov.w = fmaf(a[k], p1.y, ov.w);
    }
    ((float4*)(out + (size_t)br * D_DIM))[d] = ov;
}

// ---------------------------------------------------------------------------
extern "C" void kernel_launch(void* const* d_in, const int* in_sizes, int n_in,
                              void* d_out, int out_size)
{
    const float* x  = (const float*)d_in[0];
    const float* W1 = (const float*)d_in[1];
    const float* b1 = (const float*)d_in[2];
    const float* W2 = (const float*)d_in[3];
    float* out = (float*)d_out;

    cudaFuncSetAttribute(logits_wmma_kernel,
                         cudaFuncAttributeMaxDynamicSharedMemorySize, SMEM_TOTAL);

    prep_x_kernel<<<(NTOK_TOTAL * (D_DIM / 4)) / 256, 256>>>(x);
    prep_w_kernel<<<(D_DIM * (D_DIM / 4)) / 256, 256>>>(W1);
    logits_wmma_kernel<<<dim3(NCHUNKS, NTOK_TOTAL / BM), 128, SMEM_TOTAL>>>(b1, W2);
    pool_kernel<<<B_SZ * (N_TOK / 4), 256>>>(out);
}

// round 15
// speedup vs baseline: 1.1498x; 1.1102x over previous
#include <cuda_runtime.h>
#include <cuda_fp16.h>
#include <mma.h>
#include <cstdint>

using namespace nvcuda;

// Shape: B=16, n=4096, D=1024. Tokens = 65536.
#define B_SZ   16
#define N_TOK  4096
#define D_DIM  1024
#define NTOK_TOTAL (B_SZ * N_TOK)

#define NCHUNKS 4          // 1024 / BN
#define BM 128
#define BN 256
#define BK 32
#define KSTEPS (D_DIM / BK)   // 32

#define XPAD 40            // fp16 per x-row in smem (32 + 8 pad) = 80 B
#define WPAD 264           // fp16 per w-row in smem (256 + 8 pad) = 528 B
#define EPAD 260           // f32 per epilogue row

// Scratch (__device__ globals: allocation-free rule)
__device__ float g_part[NCHUNKS][NTOK_TOTAL];
__device__ __half g_xf[(size_t)NTOK_TOTAL * D_DIM];    // fp16(x)
__device__ __half g_Wh[D_DIM * D_DIM];                 // fp16(W1) [k][e]

// smem layout (bytes)
#define ST_XH 0                      // 128 * 80  = 10240
#define ST_WH 10240                  // 32 * 528  = 16896
#define STAGE_B 27136
#define NSLOT 4                      // 4 slots = 108544
#define EP_BYTES (BM * EPAD * 4)     // 133120 (> 4*STAGE_B) -> epilogue aliases slots
#define SM_B1 EP_BYTES               // 133120, 256 f32
#define SM_W2 (SM_B1 + 1024)
#define SMEM_TOTAL (SM_W2 + 1024)    // 135168

__device__ __forceinline__ uint32_t smem_u32(const void* p) {
    uint32_t a;
    asm("{ .reg .u64 t; cvta.to.shared.u64 t, %1; cvt.u32.u64 %0, t; }" : "=r"(a) : "l"(p));
    return a;
}
#define CP16(dst, src) \
    asm volatile("cp.async.cg.shared.global [%0], [%1], 16;" :: "r"(dst), "l"(src) : "memory")
#define CP_COMMIT() asm volatile("cp.async.commit_group;" ::: "memory")
#define CP_WAIT(n)  asm volatile("cp.async.wait_group %0;" :: "n"(n) : "memory")

// ---------------------------------------------------------------------------
// Prep: x -> fp16, W1 -> fp16.
// ---------------------------------------------------------------------------
__global__ __launch_bounds__(256)
void prep_x_kernel(const float* __restrict__ x)
{
    const size_t i4 = (size_t)blockIdx.x * 256 + threadIdx.x;   // float4 index
    float4 v = ((const float4*)x)[i4];
    ((__half2*)g_xf)[i4 * 2]     = __floats2half2_rn(v.x, v.y);
    ((__half2*)g_xf)[i4 * 2 + 1] = __floats2half2_rn(v.z, v.w);
}

__global__ __launch_bounds__(256)
void prep_w_kernel(const float* __restrict__ W1)
{
    const size_t i4 = (size_t)blockIdx.x * 256 + threadIdx.x;
    float4 v = ((const float4*)W1)[i4];
    ((__half2*)g_Wh)[i4 * 2]     = __floats2half2_rn(v.x, v.y);
    ((__half2*)g_Wh)[i4 * 2 + 1] = __floats2half2_rn(v.z, v.w);
}

// ---------------------------------------------------------------------------
// Kernel A: fp16 wmma logits GEMM, cp.async pipelined (R10 structure).
// Grid (4, 512): x = n-chunk (256 feats), y = m-tile (128 tokens).
// 8 warps, warp tile 64x64 (2m x 4n). K in 32 stages of BK=32,
// 4 smem slots, prefetch depth 3, two barriers per stage.
// ---------------------------------------------------------------------------
__global__ __launch_bounds__(256, 1)
void logits_wmma_kernel(const float* __restrict__ b1,
                        const float* __restrict__ W2)
{
    extern __shared__ char smem[];
    const uint32_t sb = smem_u32(smem);
    const int tid = threadIdx.x;
    const int wid = tid >> 5;
    const int n0  = blockIdx.x * BN;
    const int m0  = blockIdx.y * BM;

    float* s_b1 = (float*)(smem + SM_B1);
    float* s_w2 = (float*)(smem + SM_W2);
    if (tid < 256) { s_b1[tid] = b1[n0 + tid]; s_w2[tid] = W2[n0 + tid]; }

    // per-thread cp.async assignments
    // x: 128 rows x 32 fp16 = 64B/row = 4x16B chunks; 512 chunks, 2/thread
    const int xrow = tid >> 1;                  // 0..127
    const int xcc  = (tid & 1) * 2;             // chunk index base
    const size_t xg0 = (size_t)(m0 + xrow) * D_DIM + xcc * 8;
    const uint32_t xs0 = xrow * (XPAD * 2) + xcc * 16;

    auto issue_stage = [&](int kt, int slot) {
        const int k0 = kt * BK;
        const uint32_t s = sb + slot * STAGE_B;
        #pragma unroll
        for (int u = 0; u < 2; u++) {
            CP16(s + ST_XH + xs0 + u * 16, g_xf + xg0 + k0 + u * 8);
        }
        #pragma unroll
        for (int u = 0; u < 4; u++) {
            const int c  = tid * 4 + u;         // 0..1023
            const int r  = c >> 5;              // 0..31 (k row)
            const int cc = c & 31;              // 16B chunk in row
            const size_t g = (size_t)(k0 + r) * D_DIM + n0 + cc * 8;
            const uint32_t so = r * (WPAD * 2) + cc * 16;
            CP16(s + ST_WH + so, g_Wh + g);
        }
        CP_COMMIT();
    };

    // warp tile: wm in {0,1} (64 rows), wn in {0..3} (64 cols)
    const int wm = wid & 1;
    const int wn = wid >> 1;

    wmma::fragment<wmma::accumulator, 16, 16, 16, float> acc[4][4];
    #pragma unroll
    for (int i = 0; i < 4; i++)
        #pragma unroll
        for (int j = 0; j < 4; j++) wmma::fill_fragment(acc[i][j], 0.f);

    issue_stage(0, 0);
    issue_stage(1, 1);
    issue_stage(2, 2);

    #pragma unroll 2
    for (int kt = 0; kt < KSTEPS; kt++) {
        CP_WAIT(2);
        __syncthreads();
        if (kt + 3 < KSTEPS) issue_stage(kt + 3, (kt + 3) % NSLOT);
        else                 CP_COMMIT();

        const char* s = smem + (kt % NSLOT) * STAGE_B;
        const __half (*xh)[XPAD] = (const __half(*)[XPAD])(s + ST_XH);
        const __half (*wh)[WPAD] = (const __half(*)[WPAD])(s + ST_WH);

        #pragma unroll
        for (int kk = 0; kk < BK; kk += 16) {
            wmma::fragment<wmma::matrix_a, 16, 16, 16, __half, wmma::row_major> ah[4];
            #pragma unroll
            for (int i = 0; i < 4; i++)
                wmma::load_matrix_sync(ah[i], &xh[wm * 64 + i * 16][kk], XPAD);
            #pragma unroll
            for (int j = 0; j < 4; j++) {
                wmma::fragment<wmma::matrix_b, 16, 16, 16, __half, wmma::row_major> bh;
                wmma::load_matrix_sync(bh, &wh[kk][wn * 64 + j * 16], WPAD);
                #pragma unroll
                for (int i = 0; i < 4; i++)
                    wmma::mma_sync(acc[i][j], ah[i], bh, acc[i][j]);
            }
        }
        __syncthreads();
    }

    // epilogue: acc -> smem (aliases stage slots), reduce against b1/w2
    CP_WAIT(0);
    __syncthreads();
    float (*ep)[EPAD] = (float(*)[EPAD])smem;
    #pragma unroll
    for (int i = 0; i < 4; i++)
        #pragma unroll
        for (int j = 0; j < 4; j++)
            wmma::store_matrix_sync(&ep[wm * 64 + i * 16][wn * 64 + j * 16],
                                    acc[i][j], EPAD, wmma::mem_row_major);
    __syncthreads();

    const int row  = tid >> 1;
    const int half = tid & 1;
    float v = 0.f;
    #pragma unroll 8
    for (int c = 0; c < 128; c++) {
        const int e = half * 128 + c;
        float t = ep[row][e] + s_b1[e];
        t = fmaxf(t, 0.f);
        v = fmaf(t, s_w2[e], v);
    }
    v += __shfl_xor_sync(0xffffffffu, v, 1);
    if (half == 0) g_part[blockIdx.x][(size_t)m0 + row] = v;
}

// ---------------------------------------------------------------------------
// Kernel B: sum partials, 2x2 window softmax + weighted sum over fp16 x.
// (b2 omitted: softmax shift-invariant.)
// ---------------------------------------------------------------------------
__global__ __launch_bounds__(256)
void pool_kernel(float* __restrict__ out)
{
    const int br = blockIdx.x;
    const int b  = br >> 10;
    const int r  = br & 1023;
    const int i  = r >> 5;
    const int j  = r & 31;
    const int t00 = (i * 2) * 64 + (j * 2);
    const int tok[4] = {t00, t00 + 1, t00 + 64, t00 + 65};

    float l[4];
    #pragma unroll
    for (int k = 0; k < 4; k++) {
        const int t = b * N_TOK + tok[k];
        float s = 0.f;
        #pragma unroll
        for (int c = 0; c < NCHUNKS; c++) s += g_part[c][t];
        l[k] = s;
    }
    float mx = fmaxf(fmaxf(l[0], l[1]), fmaxf(l[2], l[3]));
    float e0 = __expf(l[0] - mx), e1 = __expf(l[1] - mx);
    float e2 = __expf(l[2] - mx), e3 = __expf(l[3] - mx);
    float inv = 1.f / (e0 + e1 + e2 + e3);
    const float a[4] = {e0 * inv, e1 * inv, e2 * inv, e3 * inv};

    const size_t xb = (size_t)b * N_TOK * D_DIM;
    const int d = threadIdx.x;               // 4 floats per thread
    float4 ov = {0.f, 0.f, 0.f, 0.f};
    #pragma unroll
    for (int k = 0; k < 4; k++) {
        const __half2* xr = (const __half2*)(g_xf + xb + (size_t)tok[k] * D_DIM);
        float2 p0 = __half22float2(xr[d * 2]);
        float2 p1 = __half22float2(xr[d * 2 + 1]);
        ov.x = fmaf(a[k], p0.x, ov.x);
        ov.y = fmaf(a[k], p0.y, ov.y);
        ov.z = fmaf(a[k], p1.x, ov.z);
        ov.w = fmaf(a[k], p1.y, ov.w);
    }
    ((float4*)(out + (size_t)br * D_DIM))[d] = ov;
}

// ---------------------------------------------------------------------------
extern "C" void kernel_launch(void* const* d_in, const int* in_sizes, int n_in,
                              void* d_out, int out_size)
{
    const float* x  = (const float*)d_in[0];
    const float* W1 = (const float*)d_in[1];
    const float* b1 = (const float*)d_in[2];
    const float* W2 = (const float*)d_in[3];
    float* out = (float*)d_out;

    cudaFuncSetAttribute(logits_wmma_kernel,
                         cudaFuncAttributeMaxDynamicSharedMemorySize, SMEM_TOTAL);

    prep_x_kernel<<<(NTOK_TOTAL * (D_DIM / 4)) / 256, 256>>>(x);
    prep_w_kernel<<<(D_DIM * (D_DIM / 4)) / 256, 256>>>(W1);
    logits_wmma_kernel<<<dim3(NCHUNKS, NTOK_TOTAL / BM), 256, SMEM_TOTAL>>>(b1, W2);
    pool_kernel<<<B_SZ * (N_TOK / 4), 256>>>(out);
}